// round 7
// baseline (speedup 1.0000x reference)
#include <cuda_runtime.h>
#include <math.h>

#define B 32
#define C 96
#define H 128
#define W 128
#define CR 24            // C / RED
#define KK 9             // 3x3
#define WDYN (C * KK)    // 864
#define PLANE (H * W)    // 16384

// Scratch (allocation-free requirement -> __device__ globals)
__device__ float g_pooled[B * C];
__device__ float g_wdyn[B * C * KK];

// ---------------------------------------------------------------------------
// Kernel 1: global average pool per (b,c) plane.
// grid = B*C blocks, 256 threads. float4 loads: 16384 floats = 4096 float4.
// ---------------------------------------------------------------------------
__global__ void pool_kernel(const float* __restrict__ x) {
    const int plane = blockIdx.x;                 // b*C + c
    const float4* __restrict__ p =
        reinterpret_cast<const float4*>(x + (size_t)plane * PLANE);

    float s = 0.0f;
    #pragma unroll 4
    for (int i = threadIdx.x; i < PLANE / 4; i += 256) {
        float4 v = p[i];
        s += (v.x + v.y) + (v.z + v.w);
    }

    // warp reduce
    #pragma unroll
    for (int off = 16; off > 0; off >>= 1)
        s += __shfl_xor_sync(0xffffffffu, s, off);

    __shared__ float sm[8];
    const int lane = threadIdx.x & 31;
    const int wid  = threadIdx.x >> 5;
    if (lane == 0) sm[wid] = s;
    __syncthreads();
    if (wid == 0) {
        float v = (lane < 8) ? sm[lane] : 0.0f;
        #pragma unroll
        for (int off = 4; off > 0; off >>= 1)
            v += __shfl_xor_sync(0xffffffffu, v, off);
        if (lane == 0) g_pooled[plane] = v * (1.0f / (float)PLANE);
    }
}

// ---------------------------------------------------------------------------
// Kernel 2: dynamic weight MLP per batch.
// h1 = sigmoid(BN(pooled @ w1^T));  wdyn = h1 @ w2^T + b2
// grid = B blocks, 256 threads.
// ---------------------------------------------------------------------------
__global__ void wdyn_kernel(const float* __restrict__ w1,
                            const float* __restrict__ gamma,
                            const float* __restrict__ beta,
                            const float* __restrict__ rmean,
                            const float* __restrict__ rvar,
                            const float* __restrict__ w2,
                            const float* __restrict__ b2) {
    const int b = blockIdx.x;
    const int t = threadIdx.x;

    __shared__ float sp[C];
    __shared__ float h1[CR];

    if (t < C) sp[t] = g_pooled[b * C + t];
    __syncthreads();

    if (t < CR) {
        float s = 0.0f;
        #pragma unroll 8
        for (int j = 0; j < C; j++) s += sp[j] * w1[t * C + j];
        s = (s - rmean[t]) * rsqrtf(rvar[t] + 1e-5f) * gamma[t] + beta[t];
        h1[t] = 1.0f / (1.0f + expf(-s));
    }
    __syncthreads();

    for (int i = t; i < WDYN; i += 256) {
        float s = b2[i];
        #pragma unroll
        for (int j = 0; j < CR; j++) s += h1[j] * w2[i * CR + j];
        g_wdyn[b * WDYN + i] = s;
    }
}

// ---------------------------------------------------------------------------
// Kernel 3: per-sample depthwise 3x3, stride 1, pad 1.
// Block: 128 threads, one per output column (W == 128 spans the whole plane
// width, so left/right halos are ALWAYS zero padding).
// Each block processes TB_ROWS=32 output rows of one (b,c) plane.
//
// Global loads: float4 into a shared halo tile (34 rows x 32 LDG.128).
// Compute: sliding window down the rows -- each thread keeps the 3-tap
// windows of two rows in registers and issues only 3 conflict-free scalar
// LDS per new row (lanes stride-1), 9 FMA, 1 coalesced scalar STG.
// ---------------------------------------------------------------------------
#define TB_ROWS 32
#define TILE_W  136   // 4 (left pad) + 128 + 4 (right pad); interior at [4..131]

__global__ __launch_bounds__(128) void conv_kernel(const float* __restrict__ x,
                                                   const float* __restrict__ bias,
                                                   float* __restrict__ out) {
    const int plane = blockIdx.x;               // b*C + c
    const int c     = plane % C;
    const int row0  = blockIdx.y * TB_ROWS;
    const int tx    = threadIdx.x;              // 0..127 -> output column

    const float* __restrict__ xp = x + (size_t)plane * PLANE;
    float* __restrict__ op       = out + (size_t)plane * PLANE;

    __shared__ float tile[(TB_ROWS + 2) * TILE_W];   // 34 x 136 = 18.1 KB

    // Per-plane 3x3 weights (uniform across block -> broadcast loads)
    float w[KK];
    const float* __restrict__ wp = g_wdyn + (size_t)plane * KK;
    #pragma unroll
    for (int i = 0; i < KK; i++) w[i] = __ldg(wp + i);
    const float bv = __ldg(bias + c);

    // ---- Cooperative halo load: 34 rows x 32 float4 chunks = 1088 LDG.128 ----
    #pragma unroll
    for (int idx = tx; idx < (TB_ROWS + 2) * 32; idx += 128) {
        const int r  = idx >> 5;        // tile row 0..33
        const int c4 = idx & 31;        // 16B chunk 0..31
        const int gy = row0 - 1 + r;
        float4 v = make_float4(0.f, 0.f, 0.f, 0.f);
        if (gy >= 0 && gy < H)
            v = reinterpret_cast<const float4*>(xp + gy * W)[c4];
        *reinterpret_cast<float4*>(&tile[r * TILE_W + 4 + 4 * c4]) = v;
    }
    // Zero border columns: gx = -1 at tile col [3], gx = 128 at tile col [132]
    for (int idx = tx; idx < (TB_ROWS + 2) * 2; idx += 128) {
        const int r = idx >> 1;
        tile[r * TILE_W + ((idx & 1) ? 132 : 3)] = 0.0f;
    }
    __syncthreads();

    // ---- Sliding-window compute down the 32 rows ----
    // Window of thread tx: tile cols [tx+3, tx+4, tx+5] (gx-1, gx, gx+1).
    const int cb = tx + 3;
    float a0 = tile[0 * TILE_W + cb],     a1 = tile[0 * TILE_W + cb + 1],
          a2 = tile[0 * TILE_W + cb + 2];
    float b0 = tile[1 * TILE_W + cb],     b1 = tile[1 * TILE_W + cb + 1],
          b2 = tile[1 * TILE_W + cb + 2];

    #pragma unroll
    for (int ry = 0; ry < TB_ROWS; ry++) {
        const float* rp = &tile[(ry + 2) * TILE_W + cb];
        const float c0 = rp[0], c1 = rp[1], c2 = rp[2];

        float acc = bv;
        acc = fmaf(w[0], a0, acc);
        acc = fmaf(w[1], a1, acc);
        acc = fmaf(w[2], a2, acc);
        acc = fmaf(w[3], b0, acc);
        acc = fmaf(w[4], b1, acc);
        acc = fmaf(w[5], b2, acc);
        acc = fmaf(w[6], c0, acc);
        acc = fmaf(w[7], c1, acc);
        acc = fmaf(w[8], c2, acc);
        op[(row0 + ry) * W + tx] = acc;

        a0 = b0; a1 = b1; a2 = b2;
        b0 = c0; b1 = c1; b2 = c2;
    }
}

// ---------------------------------------------------------------------------
// Launch. Input order (metadata): x, w1, gamma, beta, running_mean,
// running_var, w2, b2, bias. Output: float32 [32,96,128,128].
// ---------------------------------------------------------------------------
extern "C" void kernel_launch(void* const* d_in, const int* in_sizes, int n_in,
                              void* d_out, int out_size) {
    const float* x     = (const float*)d_in[0];
    const float* w1    = (const float*)d_in[1];
    const float* gamma = (const float*)d_in[2];
    const float* beta  = (const float*)d_in[3];
    const float* rmean = (const float*)d_in[4];
    const float* rvar  = (const float*)d_in[5];
    const float* w2    = (const float*)d_in[6];
    const float* b2    = (const float*)d_in[7];
    const float* bias  = (const float*)d_in[8];
    float* out         = (float*)d_out;

    pool_kernel<<<B * C, 256>>>(x);
    wdyn_kernel<<<B, 256>>>(w1, gamma, beta, rmean, rvar, w2, b2);
    conv_kernel<<<dim3(B * C, H / TB_ROWS), 128>>>(x, bias, out);
}

// round 9
// speedup vs baseline: 1.0930x; 1.0930x over previous
#include <cuda_runtime.h>
#include <math.h>

#define B 32
#define C 96
#define H 128
#define W 128
#define CR 24            // C / RED
#define KK 9             // 3x3
#define WDYN (C * KK)    // 864
#define PLANE (H * W)    // 16384

// Scratch (allocation-free requirement -> __device__ globals)
__device__ float g_pooled[B * C];
__device__ float g_wdyn[B * C * KK];

// ---------------------------------------------------------------------------
// Kernel 1: global average pool per (b,c) plane.
// grid = B*C blocks, 256 threads. float4 loads: 16384 floats = 4096 float4.
// Measured R7: 33.4us, DRAM 77.5% -- at practical ceiling, unchanged.
// ---------------------------------------------------------------------------
__global__ void pool_kernel(const float* __restrict__ x) {
    const int plane = blockIdx.x;                 // b*C + c
    const float4* __restrict__ p =
        reinterpret_cast<const float4*>(x + (size_t)plane * PLANE);

    float s = 0.0f;
    #pragma unroll 4
    for (int i = threadIdx.x; i < PLANE / 4; i += 256) {
        float4 v = p[i];
        s += (v.x + v.y) + (v.z + v.w);
    }

    #pragma unroll
    for (int off = 16; off > 0; off >>= 1)
        s += __shfl_xor_sync(0xffffffffu, s, off);

    __shared__ float sm[8];
    const int lane = threadIdx.x & 31;
    const int wid  = threadIdx.x >> 5;
    if (lane == 0) sm[wid] = s;
    __syncthreads();
    if (wid == 0) {
        float v = (lane < 8) ? sm[lane] : 0.0f;
        #pragma unroll
        for (int off = 4; off > 0; off >>= 1)
            v += __shfl_xor_sync(0xffffffffu, v, off);
        if (lane == 0) g_pooled[plane] = v * (1.0f / (float)PLANE);
    }
}

// ---------------------------------------------------------------------------
// Kernel 2: dynamic weight MLP per batch (negligible, ~3us).
// ---------------------------------------------------------------------------
__global__ void wdyn_kernel(const float* __restrict__ w1,
                            const float* __restrict__ gamma,
                            const float* __restrict__ beta,
                            const float* __restrict__ rmean,
                            const float* __restrict__ rvar,
                            const float* __restrict__ w2,
                            const float* __restrict__ b2) {
    const int b = blockIdx.x;
    const int t = threadIdx.x;

    __shared__ float sp[C];
    __shared__ float h1[CR];

    if (t < C) sp[t] = g_pooled[b * C + t];
    __syncthreads();

    if (t < CR) {
        float s = 0.0f;
        #pragma unroll 8
        for (int j = 0; j < C; j++) s += sp[j] * w1[t * C + j];
        s = (s - rmean[t]) * rsqrtf(rvar[t] + 1e-5f) * gamma[t] + beta[t];
        h1[t] = 1.0f / (1.0f + expf(-s));
    }
    __syncthreads();

    for (int i = t; i < WDYN; i += 256) {
        float s = b2[i];
        #pragma unroll
        for (int j = 0; j < CR; j++) s += h1[j] * w2[i * CR + j];
        g_wdyn[b * WDYN + i] = s;
    }
}

// ---------------------------------------------------------------------------
// Kernel 3: per-sample depthwise 3x3, stride 1, pad 1.
// NO shared memory. One warp processes a 32-row strip of one (b,c) plane;
// each lane owns 4 adjacent columns (lane*4 .. lane*4+3) -> a warp spans the
// full W=128 row with one LDG.128 per row. Horizontal halo via 2 SHFLs
// (lane edges; global left/right edges are zero padding since the warp spans
// the whole width). Vertical reuse: 3-row x 6-value register window, rotated
// by full unroll (register renaming, no data movement).
//
// Per row per warp: 1 LDG.128 + 2 SHFL + 36 FMA/lane + 1 STG.128.
// L1 wavefronts per 4096 outputs: ~264 (vs ~808 for the smem version that
// measured 25% off the DRAM roofline).
// ---------------------------------------------------------------------------
#define STRIP_ROWS 32
#define STRIPS_PER_PLANE (H / STRIP_ROWS)   // 4
#define CONV_BLOCK 256                      // 8 warps per block

__global__ __launch_bounds__(CONV_BLOCK) void conv_kernel(
        const float* __restrict__ x,
        const float* __restrict__ bias,
        float* __restrict__ out) {
    const int lane  = threadIdx.x & 31;
    const int gwarp = (blockIdx.x * CONV_BLOCK + threadIdx.x) >> 5;
    const int plane = gwarp >> 2;               // /STRIPS_PER_PLANE
    const int strip = gwarp & 3;
    const int row0  = strip * STRIP_ROWS;
    const int c     = plane % C;

    const float* __restrict__ xp = x + (size_t)plane * PLANE;
    float* __restrict__ op       = out + (size_t)plane * PLANE;

    float w[KK];
    const float* __restrict__ wp = g_wdyn + (size_t)plane * KK;
    #pragma unroll
    for (int i = 0; i < KK; i++) w[i] = __ldg(wp + i);
    const float bv = __ldg(bias + c);

    // 6-value row windows: [left, v0, v1, v2, v3, right]
    float A[6], Bw[6], Cw[6];

    // Load one padded row into a 6-value window.
    #define LOAD_ROW(gy, R)                                                    \
    do {                                                                       \
        float4 v = make_float4(0.f, 0.f, 0.f, 0.f);                            \
        if ((unsigned)(gy) < (unsigned)H)                                      \
            v = reinterpret_cast<const float4*>(xp + (gy) * W)[lane];          \
        float l = __shfl_up_sync(0xffffffffu, v.w, 1);                         \
        float r = __shfl_down_sync(0xffffffffu, v.x, 1);                       \
        (R)[0] = (lane == 0)  ? 0.0f : l;                                      \
        (R)[1] = v.x; (R)[2] = v.y; (R)[3] = v.z; (R)[4] = v.w;                \
        (R)[5] = (lane == 31) ? 0.0f : r;                                      \
    } while (0)

    LOAD_ROW(row0 - 1, A);
    LOAD_ROW(row0,     Bw);

    #pragma unroll
    for (int ry = 0; ry < STRIP_ROWS; ry++) {
        LOAD_ROW(row0 + ry + 1, Cw);

        float4 o;
        float* ov = &o.x;
        #pragma unroll
        for (int j = 0; j < 4; j++) {
            float acc = bv;
            acc = fmaf(w[0], A[j + 0], acc);
            acc = fmaf(w[1], A[j + 1], acc);
            acc = fmaf(w[2], A[j + 2], acc);
            acc = fmaf(w[3], Bw[j + 0], acc);
            acc = fmaf(w[4], Bw[j + 1], acc);
            acc = fmaf(w[5], Bw[j + 2], acc);
            acc = fmaf(w[6], Cw[j + 0], acc);
            acc = fmaf(w[7], Cw[j + 1], acc);
            acc = fmaf(w[8], Cw[j + 2], acc);
            ov[j] = acc;
        }
        reinterpret_cast<float4*>(op + (row0 + ry) * W)[lane] = o;

        #pragma unroll
        for (int i = 0; i < 6; i++) { A[i] = Bw[i]; Bw[i] = Cw[i]; }
    }
    #undef LOAD_ROW
}

// ---------------------------------------------------------------------------
// Launch. Input order (metadata): x, w1, gamma, beta, running_mean,
// running_var, w2, b2, bias. Output: float32 [32,96,128,128].
// ---------------------------------------------------------------------------
extern "C" void kernel_launch(void* const* d_in, const int* in_sizes, int n_in,
                              void* d_out, int out_size) {
    const float* x     = (const float*)d_in[0];
    const float* w1    = (const float*)d_in[1];
    const float* gamma = (const float*)d_in[2];
    const float* beta  = (const float*)d_in[3];
    const float* rmean = (const float*)d_in[4];
    const float* rvar  = (const float*)d_in[5];
    const float* w2    = (const float*)d_in[6];
    const float* b2    = (const float*)d_in[7];
    const float* bias  = (const float*)d_in[8];
    float* out         = (float*)d_out;

    pool_kernel<<<B * C, 256>>>(x);
    wdyn_kernel<<<B, 256>>>(w1, gamma, beta, rmean, rvar, w2, b2);

    const int total_warps = B * C * STRIPS_PER_PLANE;          // 12288
    conv_kernel<<<total_warps * 32 / CONV_BLOCK, CONV_BLOCK>>>(x, bias, out);
}